// round 3
// baseline (speedup 1.0000x reference)
#include <cuda_runtime.h>
#include <cuda_bf16.h>
#include <cstdint>

#define D 128
#define MAX_NODES 50000

// Scratch for the segment-sum (no device allocs allowed -> static __device__).
__device__ float g_aggr[(size_t)MAX_NODES * D];

// ---------------------------------------------------------------------------
// Kernel 1: zero the aggregation scratch (float4 stores).
// ---------------------------------------------------------------------------
__global__ void zero_kernel(float4* __restrict__ p, int n4) {
    int i = blockIdx.x * blockDim.x + threadIdx.x;
    if (i < n4) p[i] = make_float4(0.f, 0.f, 0.f, 0.f);
}

// ---------------------------------------------------------------------------
// Kernel 2: edge scatter. One warp per edge:
//   lane l: v = x[src][4l..4l+3];  red.global.add.v4.f32 aggr[dst][4l..4l+3] += v
// x (25.6 MB) fits in L2, so gathers are L2 hits; v4 reds quarter the
// atomic-op count vs scalar atomicAdd.
// ---------------------------------------------------------------------------
__global__ void scatter_kernel(const float* __restrict__ x,
                               const int* __restrict__ esrc,
                               const int* __restrict__ edst,
                               float* __restrict__ aggr, int E) {
    int gid = blockIdx.x * blockDim.x + threadIdx.x;
    int e = gid >> 5;
    int lane = gid & 31;
    if (e >= E) return;
    int s = __ldg(&esrc[e]);
    int d = __ldg(&edst[e]);
    const float4* xr = reinterpret_cast<const float4*>(x + (size_t)s * D);
    float4 v = __ldg(&xr[lane]);
    float* ap = aggr + (size_t)d * D + lane * 4;
    asm volatile("red.global.add.v4.f32 [%0], {%1, %2, %3, %4};"
                 :: "l"(ap), "f"(v.x), "f"(v.y), "f"(v.z), "f"(v.w)
                 : "memory");
}

// ---------------------------------------------------------------------------
// Kernel 3: fused GEMM.
//   out[n][o] = sum_d x[n][d]*W1[o][d] + sum_d aggr[n][d]*W2[o][d] + b1[o]+b2[o]
// Treated as M x 128 GEMM with K=256 (concat of x|aggr vs W1|W2).
// Both weight matrices live (transposed, padded) in smem for the whole block;
// x/aggr rows stream through a 128x32 smem tile. 512 threads, 8x4 register
// tile per thread (rows: tr*8+i, cols: tc + 32*j -> conflict-free LDS and
// coalesced STG).
// ---------------------------------------------------------------------------
#define BM 128
#define NT 512
#define LDW 129   // Wt row pad: write bank = (k+o)%32, read lanes consecutive
#define LDX 33    // xs row pad

__global__ __launch_bounds__(NT, 1)
void gemm_kernel(const float* __restrict__ x, const float* __restrict__ aggr,
                 const float* __restrict__ W1, const float* __restrict__ W2,
                 const float* __restrict__ b1, const float* __restrict__ b2,
                 float* __restrict__ out, int N) {
    extern __shared__ float sm[];
    float* Wt = sm;                    // [256][LDW]  (k-major, transposed W)
    float* xs = sm + 256 * LDW;        // [BM][LDX]

    int tid = threadIdx.x;

    // Load Wt[k][o] = W[o][k] for W1 (k: 0..127) and W2 (k: 128..255).
    // Global reads coalesced (k fast within a W row); smem writes stride LDW
    // floats -> bank (k + o) % 32, k varies across lanes -> conflict-free.
    for (int i = tid; i < D * D; i += NT) {
        int o = i >> 7;
        int k = i & (D - 1);
        float w1 = W1[i];
        float w2 = W2[i];
        Wt[k * LDW + o] = w1;
        Wt[(k + D) * LDW + o] = w2;
    }

    int row0 = blockIdx.x * BM;
    int tc = tid & 31;    // col group: cols tc, tc+32, tc+64, tc+96
    int tr = tid >> 5;    // row group: rows tr*8 .. tr*8+7

    float acc[8][4];
#pragma unroll
    for (int i = 0; i < 8; i++)
#pragma unroll
        for (int j = 0; j < 4; j++) acc[i][j] = 0.f;

    // K = 256 in 8 chunks of 32: chunks 0-3 from x, 4-7 from aggr.
#pragma unroll 1
    for (int kc = 0; kc < 8; kc++) {
        const float* src = (kc < 4) ? x : aggr;
        int k0 = (kc & 3) * 32;

        __syncthreads();   // previous chunk's compute done before overwrite
        for (int i = tid; i < BM * 32; i += NT) {
            int r = i >> 5;
            int kk = i & 31;
            int grow = row0 + r;
            xs[r * LDX + kk] = (grow < N) ? src[(size_t)grow * D + k0 + kk] : 0.f;
        }
        __syncthreads();   // xs (and, for kc==0, Wt) visible

        int kwbase = kc * 32;
#pragma unroll
        for (int kk = 0; kk < 32; kk++) {
            float b[4];
            const float* wrow = &Wt[(kwbase + kk) * LDW];
#pragma unroll
            for (int j = 0; j < 4; j++) b[j] = wrow[tc + 32 * j];
#pragma unroll
            for (int i = 0; i < 8; i++) {
                float a = xs[(tr * 8 + i) * LDX + kk];   // broadcast across warp
#pragma unroll
                for (int j = 0; j < 4; j++) acc[i][j] += a * b[j];
            }
        }
    }

    // Epilogue: add (b1+b2), write coalesced.
#pragma unroll
    for (int j = 0; j < 4; j++) {
        int o = tc + 32 * j;
        float bias = __ldg(&b1[o]) + __ldg(&b2[o]);
#pragma unroll
        for (int i = 0; i < 8; i++) {
            int grow = row0 + tr * 8 + i;
            if (grow < N) out[(size_t)grow * D + o] = acc[i][j] + bias;
        }
    }
}

// ---------------------------------------------------------------------------
// launch
// ---------------------------------------------------------------------------
extern "C" void kernel_launch(void* const* d_in, const int* in_sizes, int n_in,
                              void* d_out, int out_size) {
    const float* x    = (const float*)d_in[0];   // [N, 128]
    const float* W1   = (const float*)d_in[1];   // [128, 128]
    const float* b1   = (const float*)d_in[2];   // [128]
    const float* W2   = (const float*)d_in[3];   // [128, 128]
    const float* b2   = (const float*)d_in[4];   // [128]
    const int*   esrc = (const int*)d_in[5];     // [E]
    const int*   edst = (const int*)d_in[6];     // [E]
    float* out = (float*)d_out;

    int N = in_sizes[0] / D;
    int E = in_sizes[5];
    if (N > MAX_NODES) N = MAX_NODES;

    float* aggr = nullptr;
    cudaGetSymbolAddress((void**)&aggr, g_aggr);

    // 1) zero aggr
    {
        int n4 = N * (D / 4);
        int threads = 256;
        int blocks = (n4 + threads - 1) / threads;
        zero_kernel<<<blocks, threads>>>((float4*)aggr, n4);
    }

    // 2) edge scatter (one warp per edge)
    {
        int threads = 256;
        long long total = (long long)E * 32;
        int blocks = (int)((total + threads - 1) / threads);
        scatter_kernel<<<blocks, threads>>>(x, esrc, edst, aggr, E);
    }

    // 3) fused GEMM
    {
        size_t smem = (256 * LDW + BM * LDX) * sizeof(float);
        static bool attr_set = false;  // idempotent attribute; safe under capture
        cudaFuncSetAttribute(gemm_kernel,
                             cudaFuncAttributeMaxDynamicSharedMemorySize,
                             (int)smem);
        int blocks = (N + BM - 1) / BM;
        gemm_kernel<<<blocks, NT, smem>>>(x, aggr, W1, W2, b1, b2, out, N);
        (void)attr_set;
    }
}

// round 7
// speedup vs baseline: 1.2770x; 1.2770x over previous
#include <cuda_runtime.h>
#include <cuda_bf16.h>
#include <cstdint>

#define D 128
#define MAX_NODES 50000

// Scratch for the segment-sum (no device allocs allowed -> static __device__).
__device__ float g_aggr[(size_t)MAX_NODES * D];

// ---------------------------------------------------------------------------
// Kernel 1: zero the aggregation scratch.
// ---------------------------------------------------------------------------
__global__ void zero_kernel(float4* __restrict__ p, int n4) {
    int i = blockIdx.x * blockDim.x + threadIdx.x;
    if (i < n4) p[i] = make_float4(0.f, 0.f, 0.f, 0.f);
}

// ---------------------------------------------------------------------------
// Kernel 2: edge scatter. One warp per edge, red.global.add.v4.f32.
// x (25.6 MB) is L2-resident; v4 reds quarter the atomic-op count.
// ---------------------------------------------------------------------------
__global__ void scatter_kernel(const float* __restrict__ x,
                               const int* __restrict__ esrc,
                               const int* __restrict__ edst,
                               float* __restrict__ aggr, int E) {
    int gid = blockIdx.x * blockDim.x + threadIdx.x;
    int e = gid >> 5;
    int lane = gid & 31;
    if (e >= E) return;
    int s = __ldg(&esrc[e]);
    int d = __ldg(&edst[e]);
    const float4* xr = reinterpret_cast<const float4*>(x + (size_t)s * D);
    float4 v = __ldg(&xr[lane]);
    float* ap = aggr + (size_t)d * D + lane * 4;
    asm volatile("red.global.add.v4.f32 [%0], {%1, %2, %3, %4};"
                 :: "l"(ap), "f"(v.x), "f"(v.y), "f"(v.z), "f"(v.w)
                 : "memory");
}

// ---------------------------------------------------------------------------
// Kernel 3: tf32 mma.sync GEMM (sm_80+ baseline PTX -> works at compute_103).
//   out[n][o] = sum_k [x|aggr][n][k] * [W1|W2][o][k] + (b1+b2)[o]
// CTA: BM=128 rows, BN=128 cols, K=256 in 8 chunks of 32.
// 8 warps, warp tile 32x64 = 2 m-frags x 8 n-frags of m16n8k8.
// fp32 accumulate in registers; inputs rounded to tf32 (cvt.rna) in smem.
// ---------------------------------------------------------------------------
#define BM 128
#define GT 256
#define LDA 33

__device__ __forceinline__ float to_tf32(float f) {
    uint32_t u;
    asm("cvt.rna.tf32.f32 %0, %1;" : "=r"(u) : "f"(f));
    return __uint_as_float(u);
}

__device__ __forceinline__ void mma1688(float* c, const uint32_t* a,
                                        const uint32_t* b) {
    asm volatile(
        "mma.sync.aligned.m16n8k8.row.col.f32.tf32.tf32.f32 "
        "{%0,%1,%2,%3}, {%4,%5,%6,%7}, {%8,%9}, {%0,%1,%2,%3};"
        : "+f"(c[0]), "+f"(c[1]), "+f"(c[2]), "+f"(c[3])
        : "r"(a[0]), "r"(a[1]), "r"(a[2]), "r"(a[3]), "r"(b[0]), "r"(b[1]));
}

__global__ __launch_bounds__(GT, 1)
void gemm_mma(const float* __restrict__ x, const float* __restrict__ aggr,
              const float* __restrict__ W1, const float* __restrict__ W2,
              const float* __restrict__ b1, const float* __restrict__ b2,
              float* __restrict__ out, int N) {
    __shared__ float As[BM][LDA];     // [row][k]
    __shared__ float Bs[128][LDA];    // [out-col][k]
    __shared__ float sbias[128];

    int tid = threadIdx.x;
    int warp = tid >> 5, lane = tid & 31;
    int wm = warp & 3;          // row block: rows wm*32 .. +31
    int wn = warp >> 2;         // col block: cols wn*64 .. +63
    int g = lane >> 2;          // groupID
    int t = lane & 3;           // threadID_in_group
    int row0 = blockIdx.x * BM;

    if (tid < 128) sbias[tid] = __ldg(&b1[tid]) + __ldg(&b2[tid]);

    float acc[2][8][4];
#pragma unroll
    for (int mi = 0; mi < 2; mi++)
#pragma unroll
        for (int ni = 0; ni < 8; ni++)
#pragma unroll
            for (int c = 0; c < 4; c++) acc[mi][ni][c] = 0.f;

#pragma unroll 1
    for (int kb = 0; kb < 8; kb++) {
        const float* asrc = (kb < 4) ? x : aggr;
        const float* bsrc = (kb < 4) ? W1 : W2;
        int k0 = (kb & 3) * 32;

        __syncthreads();
        // Fill As (128x32) and Bs (128x32); 4 float4 each per thread.
#pragma unroll
        for (int i = 0; i < 4; i++) {
            int f = tid + i * GT;
            int r = f >> 3, c = (f & 7) * 4;
            int grow = row0 + r;
            float4 v = make_float4(0.f, 0.f, 0.f, 0.f);
            if (grow < N)
                v = *reinterpret_cast<const float4*>(asrc + (size_t)grow * D + k0 + c);
            As[r][c + 0] = to_tf32(v.x);
            As[r][c + 1] = to_tf32(v.y);
            As[r][c + 2] = to_tf32(v.z);
            As[r][c + 3] = to_tf32(v.w);
            float4 w = *reinterpret_cast<const float4*>(bsrc + (size_t)r * D + k0 + c);
            Bs[r][c + 0] = to_tf32(w.x);
            Bs[r][c + 1] = to_tf32(w.y);
            Bs[r][c + 2] = to_tf32(w.z);
            Bs[r][c + 3] = to_tf32(w.w);
        }
        __syncthreads();

#pragma unroll
        for (int ks = 0; ks < 4; ks++) {
            int k8 = ks * 8;
            uint32_t a[2][4];
#pragma unroll
            for (int mi = 0; mi < 2; mi++) {
                int rb = wm * 32 + mi * 16;
                a[mi][0] = __float_as_uint(As[rb + g][k8 + t]);
                a[mi][1] = __float_as_uint(As[rb + g + 8][k8 + t]);
                a[mi][2] = __float_as_uint(As[rb + g][k8 + t + 4]);
                a[mi][3] = __float_as_uint(As[rb + g + 8][k8 + t + 4]);
            }
            uint32_t b[8][2];
#pragma unroll
            for (int ni = 0; ni < 8; ni++) {
                int cb = wn * 64 + ni * 8;
                b[ni][0] = __float_as_uint(Bs[cb + g][k8 + t]);
                b[ni][1] = __float_as_uint(Bs[cb + g][k8 + t + 4]);
            }
#pragma unroll
            for (int mi = 0; mi < 2; mi++)
#pragma unroll
                for (int ni = 0; ni < 8; ni++)
                    mma1688(acc[mi][ni], a[mi], b[ni]);
        }
    }

    // Epilogue: c0,c1 -> row g, cols t*2,t*2+1; c2,c3 -> row g+8.
#pragma unroll
    for (int mi = 0; mi < 2; mi++) {
        int r_lo = row0 + wm * 32 + mi * 16 + g;
#pragma unroll
        for (int ni = 0; ni < 8; ni++) {
            int col = wn * 64 + ni * 8 + t * 2;
            float bx = sbias[col], by = sbias[col + 1];
            if (r_lo < N) {
                float2 v = make_float2(acc[mi][ni][0] + bx, acc[mi][ni][1] + by);
                *reinterpret_cast<float2*>(out + (size_t)r_lo * D + col) = v;
            }
            if (r_lo + 8 < N) {
                float2 v = make_float2(acc[mi][ni][2] + bx, acc[mi][ni][3] + by);
                *reinterpret_cast<float2*>(out + (size_t)(r_lo + 8) * D + col) = v;
            }
        }
    }
}

// ---------------------------------------------------------------------------
// launch
// ---------------------------------------------------------------------------
extern "C" void kernel_launch(void* const* d_in, const int* in_sizes, int n_in,
                              void* d_out, int out_size) {
    const float* x    = (const float*)d_in[0];   // [N, 128]
    const float* W1   = (const float*)d_in[1];   // [128, 128]
    const float* b1   = (const float*)d_in[2];   // [128]
    const float* W2   = (const float*)d_in[3];   // [128, 128]
    const float* b2   = (const float*)d_in[4];   // [128]
    const int*   esrc = (const int*)d_in[5];     // [E]
    const int*   edst = (const int*)d_in[6];     // [E]
    float* out = (float*)d_out;

    int N = in_sizes[0] / D;
    int E = in_sizes[5];
    if (N > MAX_NODES) N = MAX_NODES;

    float* aggr = nullptr;
    cudaGetSymbolAddress((void**)&aggr, g_aggr);

    // 1) zero aggr
    {
        int n4 = N * (D / 4);
        int threads = 256;
        int blocks = (n4 + threads - 1) / threads;
        zero_kernel<<<blocks, threads>>>((float4*)aggr, n4);
    }

    // 2) edge scatter (one warp per edge)
    {
        int threads = 256;
        long long total = (long long)E * 32;
        int blocks = (int)((total + threads - 1) / threads);
        scatter_kernel<<<blocks, threads>>>(x, esrc, edst, aggr, E);
    }

    // 3) tf32 mma.sync GEMM
    {
        int blocks = (N + BM - 1) / BM;
        gemm_mma<<<blocks, GT>>>(x, aggr, W1, W2, b1, b2, out, N);
    }
}